// round 3
// baseline (speedup 1.0000x reference)
#include <cuda_runtime.h>
#include <math.h>

#define DD 128
static const int NC = DD * DD * DD;   // cells per layer

// smem: 6 fields x (TZ+2)=4 z x (TY+2)=6 y x 128 floats
#define F_STRIDE (4 * 6 * 128)        // 3072 floats per field
#define SMEM_FLOATS (6 * F_STRIDE)    // 18432 floats = 73728 B

typedef unsigned long long f2;        // packed f32x2 in a 64-bit reg pair

__device__ __forceinline__ f2 pk(float lo, float hi) {
    f2 r; asm("mov.b64 %0,{%1,%2};" : "=l"(r) : "f"(lo), "f"(hi)); return r;
}
__device__ __forceinline__ void up(f2 v, float& lo, float& hi) {
    asm("mov.b64 {%0,%1},%2;" : "=f"(lo), "=f"(hi) : "l"(v));
}
__device__ __forceinline__ f2 fma2(f2 a, f2 b, f2 c) {
    f2 d; asm("fma.rn.f32x2 %0,%1,%2,%3;" : "=l"(d) : "l"(a), "l"(b), "l"(c)); return d;
}
__device__ __forceinline__ f2 mul2(f2 a, f2 b) {
    f2 d; asm("mul.rn.f32x2 %0,%1,%2;" : "=l"(d) : "l"(a), "l"(b)); return d;
}
__device__ __forceinline__ float rsqrt_fast(float x) {
    float y; asm("rsqrt.approx.f32 %0, %1;" : "=f"(y) : "f"(x)); return y;
}

__device__ __forceinline__ float boundary_force(float p, float v, float mv, float ETAf) {
    float lo = (p > 0.1f && p < 0.15f) ? mv : 0.0f;
    float hi = (p > 12.65f) ? mv : 0.0f;
    float fb = 6.0e6f * lo * (0.15f - p);
    fb -= 6.0e6f * hi * (((p - 12.8f) + 0.1f) + 0.05f);
    fb -= ETAf * v * lo;
    fb -= ETAf * v * hi;
    return fb;
}

struct Consts { f2 NEG1, EPS2, KN2, NKPS2, ETA2; };

// One packed interaction: 2 cells (packed centers C[0..5]) vs one window column
// supplied as 12 scalars, packed just-in-time (keeps live-register count low).
__device__ __forceinline__ void interact(
    const f2* __restrict__ C,
    float wxl, float wxh, float wyl, float wyh, float wzl, float wzh,
    float wvxl, float wvxh, float wvyl, float wvyh, float wvzl, float wvzh,
    f2& FX, f2& FY, f2& FZ, const Consts& K)
{
    f2 dx2 = fma2(pk(wxl, wxh), K.NEG1, C[0]);
    f2 dy2 = fma2(pk(wyl, wyh), K.NEG1, C[1]);
    f2 dz2 = fma2(pk(wzl, wzh), K.NEG1, C[2]);
    f2 s2  = fma2(dz2, dz2, K.EPS2);    // +1e-8 floor folded in
    s2 = fma2(dy2, dy2, s2);
    s2 = fma2(dx2, dx2, s2);
    float s0, s1; up(s2, s0, s1);
    float r0 = rsqrt_fast(s0);
    float r1 = rsqrt_fast(s1);
    r0 = (s0 < 0.01f) ? r0 : 0.0f;      // contact gate folded into r
    r1 = (s1 < 0.01f) ? r1 : 0.0f;
    f2 rg = pk(r0, r1);
    f2 dist2 = mul2(s2, rg);            // = sqrt(s2) where gated-in, else 0
    f2 dvx2 = fma2(pk(wvxl, wvxh), K.NEG1, C[3]);
    f2 dvy2 = fma2(pk(wvyl, wvyh), K.NEG1, C[4]);
    f2 dvz2 = fma2(pk(wvzl, wvzh), K.NEG1, C[5]);
    f2 dot2 = mul2(dvz2, dz2);
    dot2 = fma2(dvy2, dy2, dot2);
    dot2 = fma2(dvx2, dx2, dot2);
    f2 q2 = mul2(dot2, rg);             // dvn / dc  (dc clamp automatic: r<=1e4)
    f2 t2 = fma2(K.KN2, dist2, K.NKPS2);  // KN*(dist-PS)
    t2 = fma2(K.ETA2, q2, t2);
    f2 coef2 = mul2(t2, rg);            // zero where gated-out
    FX = fma2(coef2, dx2, FX);
    FY = fma2(coef2, dy2, FY);
    FZ = fma2(coef2, dz2, FZ);
}

// window value j (0..5) of field f from quad + shuffle edges
#define WIN(f, j) ((j) == 0 ? s0_[f] : (j) == 1 ? q_[f].x : (j) == 2 ? q_[f].y : \
                   (j) == 3 ? q_[f].z : (j) == 4 ? q_[f].w : s5_[f])

__global__ void __launch_bounds__(256, 2)
dem_pass(const float* __restrict__ x0, const float* __restrict__ y0, const float* __restrict__ z0,
         const float* __restrict__ x1, const float* __restrict__ y1, const float* __restrict__ z1,
         const float* __restrict__ vxl0, const float* __restrict__ vyl0, const float* __restrict__ vzl0,
         const float* __restrict__ vxl1, const float* __restrict__ vyl1, const float* __restrict__ vzl1,
         const float* __restrict__ cx, const float* __restrict__ cy, const float* __restrict__ cz,
         const float* __restrict__ cvx, const float* __restrict__ cvy, const float* __restrict__ cvz,
         const float* __restrict__ cmask,
         float* __restrict__ ovx, float* __restrict__ ovy, float* __restrict__ ovz,
         float ETAf, float DTPMf, float GPMf)
{
    extern __shared__ float sm[];

    const int lane = threadIdx.x;                    // 0..31, x-quads
    const int ty = threadIdx.y;                      // 0..3
    const int tz = threadIdx.z;                      // 0..1
    const int tid = (tz * 4 + ty) * 32 + lane;       // 0..255
    const int by0 = blockIdx.x * 4;                  // y tile base
    const int bz0 = blockIdx.y * 2;                  // z tile base
    const int yc = by0 + ty;
    const int zc = bz0 + tz;
    const int base = (zc * DD + yc) * DD + lane * 4; // center cell (first of quad)

    Consts K;
    K.NEG1  = pk(-1.0f, -1.0f);
    K.EPS2  = pk(1e-8f, 1e-8f);
    K.KN2   = pk(6.0e6f, 6.0e6f);
    K.NKPS2 = pk(-600000.0f, -600000.0f);
    K.ETA2  = pk(ETAf, ETAf);

    // center values (layer n)
    float4 xn4  = *reinterpret_cast<const float4*>(cx + base);
    float4 yn4  = *reinterpret_cast<const float4*>(cy + base);
    float4 zn4  = *reinterpret_cast<const float4*>(cz + base);
    float4 vxn4 = *reinterpret_cast<const float4*>(cvx + base);
    float4 vyn4 = *reinterpret_cast<const float4*>(cvy + base);
    float4 vzn4 = *reinterpret_cast<const float4*>(cvz + base);
    float4 mk4  = *reinterpret_cast<const float4*>(cmask + base);

    f2 C0[6] = { pk(xn4.x, xn4.y), pk(yn4.x, yn4.y), pk(zn4.x, zn4.y),
                 pk(vxn4.x, vxn4.y), pk(vyn4.x, vyn4.y), pk(vzn4.x, vzn4.y) };
    f2 C1[6] = { pk(xn4.z, xn4.w), pk(yn4.z, yn4.w), pk(zn4.z, zn4.w),
                 pk(vxn4.z, vxn4.w), pk(vyn4.z, vyn4.w), pk(vzn4.z, vzn4.w) };

    f2 FX0 = 0, FY0 = 0, FZ0 = 0;     // accumulators for cells (0,1)
    f2 FX1 = 0, FY1 = 0, FZ1 = 0;     // accumulators for cells (2,3)

#pragma unroll
    for (int m = 0; m < 2; ++m) {
        const float* Ps[6];
        Ps[0] = m ? x1 : x0;   Ps[1] = m ? y1 : y0;   Ps[2] = m ? z1 : z0;
        Ps[3] = m ? vxl1 : vxl0; Ps[4] = m ? vyl1 : vyl0; Ps[5] = m ? vzl1 : vzl0;

        if (m) __syncthreads();   // protect previous phase's reads before overwrite

        // cooperative tile load: 24 rows (4z x 6y) of 128 floats per field
#pragma unroll
        for (int f = 0; f < 6; ++f) {
            const float* p = Ps[f];
            float* s = sm + f * F_STRIDE;
#pragma unroll
            for (int it = 0; it < 3; ++it) {
                int t = tid + it * 256;            // 0..767 (float4 granules)
                int row = t >> 5;
                int l = t & 31;
                int lz = row / 6;
                int ly = row - lz * 6;
                int gz = (bz0 + lz - 1) & 127;
                int gy = (by0 + ly - 1) & 127;
                *reinterpret_cast<float4*>(s + row * 128 + l * 4) =
                    *reinterpret_cast<const float4*>(p + (gz * DD + gy) * DD + l * 4);
            }
        }
        __syncthreads();

        // 3x3 (z,y) rows; per row, a 6-wide x-window gives 3 shifts per cell pair
#pragma unroll
        for (int dz = 0; dz < 3; ++dz) {
#pragma unroll
            for (int dy = 0; dy < 3; ++dy) {
                const int roff = ((tz + dz) * 6 + (ty + dy)) * 128 + lane * 4;
                float4 q_[6];
                float s0_[6], s5_[6];
#pragma unroll
                for (int f = 0; f < 6; ++f) {
                    q_[f] = *reinterpret_cast<const float4*>(sm + f * F_STRIDE + roff);
                    // circular warp shuffle = periodic x wrap (warp covers full x axis)
                    s0_[f] = __shfl_sync(0xffffffffu, q_[f].w, (lane + 31) & 31);
                    s5_[f] = __shfl_sync(0xffffffffu, q_[f].x, (lane + 1) & 31);
                }
                // interleave L-pair (windows j,j+1) and H-pair (windows j+2,j+3)
#pragma unroll
                for (int j = 0; j < 3; ++j) {
                    interact(C0,
                             WIN(0, j), WIN(0, j + 1), WIN(1, j), WIN(1, j + 1),
                             WIN(2, j), WIN(2, j + 1), WIN(3, j), WIN(3, j + 1),
                             WIN(4, j), WIN(4, j + 1), WIN(5, j), WIN(5, j + 1),
                             FX0, FY0, FZ0, K);
                    interact(C1,
                             WIN(0, j + 2), WIN(0, j + 3), WIN(1, j + 2), WIN(1, j + 3),
                             WIN(2, j + 2), WIN(2, j + 3), WIN(3, j + 2), WIN(3, j + 3),
                             WIN(4, j + 2), WIN(4, j + 3), WIN(5, j + 2), WIN(5, j + 3),
                             FX1, FY1, FZ1, K);
                }
            }
        }
    }

    // unpack accumulators
    float fxa[4], fya[4], fza[4];
    up(FX0, fxa[0], fxa[1]); up(FX1, fxa[2], fxa[3]);
    up(FY0, fya[0], fya[1]); up(FY1, fya[2], fya[3]);
    up(FZ0, fza[0], fza[1]); up(FZ1, fza[2], fza[3]);

    const float xn[4]  = {xn4.x, xn4.y, xn4.z, xn4.w};
    const float yn[4]  = {yn4.x, yn4.y, yn4.z, yn4.w};
    const float zn[4]  = {zn4.x, zn4.y, zn4.z, zn4.w};
    const float vxn[4] = {vxn4.x, vxn4.y, vxn4.z, vxn4.w};
    const float vyn[4] = {vyn4.x, vyn4.y, vyn4.z, vyn4.w};
    const float vzn[4] = {vzn4.x, vzn4.y, vzn4.z, vzn4.w};
    const float mk[4]  = {mk4.x, mk4.y, mk4.z, mk4.w};

    float outx[4], outy[4], outz[4];
#pragma unroll
    for (int c = 0; c < 4; ++c) {
        float mv = mk[c];
        float fxb = boundary_force(xn[c], vxn[c], mv, ETAf);
        float fyb = boundary_force(yn[c], vyn[c], mv, ETAf);
        float fzb = boundary_force(zn[c], vzn[c], mv, ETAf);
        float sc = DTPMf * mv;
        outx[c] = vxn[c] + sc * (fxb - fxa[c]);
        outy[c] = vyn[c] + sc * (fyb - fya[c]);
        outz[c] = vzn[c] + sc * ((GPMf - fza[c]) + fzb);
    }
    *reinterpret_cast<float4*>(ovx + base) = make_float4(outx[0], outx[1], outx[2], outx[3]);
    *reinterpret_cast<float4*>(ovy + base) = make_float4(outy[0], outy[1], outy[2], outy[3]);
    *reinterpret_cast<float4*>(ovz + base) = make_float4(outz[0], outz[1], outz[2], outz[3]);
}

extern "C" void kernel_launch(void* const* d_in, const int* in_sizes, int n_in,
                              void* d_out, int out_size)
{
    const float* x  = (const float*)d_in[0];
    const float* y  = (const float*)d_in[1];
    const float* z  = (const float*)d_in[2];
    const float* vx = (const float*)d_in[3];
    const float* vy = (const float*)d_in[4];
    const float* vz = (const float*)d_in[5];
    const float* mask = (const float*)d_in[6];
    float* out = (float*)d_out;
    const int N = NC;

    const double PI = 3.141592653589793;
    const double ALPHA = 0.6931471805599453 / PI;          // -log(0.5)/pi
    const double GAMMA = ALPHA / sqrt(ALPHA * ALPHA + 1.0);
    const double PM = 4.0 / 3.0 * 3.1415 * (0.1 * 0.1 * 0.1) * 2700.0;
    const double ETA = 2.0 * GAMMA * sqrt(6.0e6 * PM);
    const float ETAf  = (float)ETA;
    const float DTPMf = (float)(1e-4 / PM);
    const float GPMf  = (float)(-9.8 * PM);

    cudaFuncSetAttribute(dem_pass, cudaFuncAttributeMaxDynamicSharedMemorySize,
                         SMEM_FLOATS * (int)sizeof(float));

    dim3 grid(32, 64);      // 128/4 y-tiles, 128/2 z-tiles
    dim3 block(32, 4, 2);
    size_t shmem = SMEM_FLOATS * sizeof(float);

    // pass n = 0: neighbors use original velocities of both layers
    dem_pass<<<grid, block, shmem>>>(
        x, y, z, x + N, y + N, z + N,
        vx, vy, vz, vx + N, vy + N, vz + N,
        x, y, z, vx, vy, vz,
        mask,
        out + 0 * N, out + 2 * N, out + 4 * N,
        ETAf, DTPMf, GPMf);

    // pass n = 1: layer-0 neighbor velocities come from updated output
    dem_pass<<<grid, block, shmem>>>(
        x, y, z, x + N, y + N, z + N,
        out + 0 * N, out + 2 * N, out + 4 * N,
        vx + N, vy + N, vz + N,
        x + N, y + N, z + N, vx + N, vy + N, vz + N,
        mask + N,
        out + 1 * N, out + 3 * N, out + 5 * N,
        ETAf, DTPMf, GPMf);
}